// round 13
// baseline (speedup 1.0000x reference)
#include <cuda_runtime.h>
#include <cuda_bf16.h>
#include <cstdint>

#define N_PP 8192
#define DIM  16
#define L2E  1.4426950408889634f

#define TPB      256
#define ROWS_PT  128                 // rows per tile (8 warps x m16)
#define COLS_PT  256                 // cols per tile (32 n8 subtiles)
#define NB_ROW   64
#define NB_COL   32
#define N_PP_ACT 1056                // cb >= rb>>1
#define N_AP_T   (NB_ROW * NB_COL)   // 2048
#define N_EDGE_T 104
#define NB_TOTAL (N_PP_ACT + N_AP_T + N_EDGE_T)   // 3208

// smem layout: swizzled 128B rows
#define SM_A   0                     // 128 x 128B = 16384
#define SM_B   16384                 // 256 x 128B = 32768
#define SM_LW  49152                 // 256 floats = 1024
#define SM_RED 50176
#define SMEM_TOTAL (SM_RED + 64)

// row records: 128B = [hi bf16 x32 | lo bf16 x32] (8 x uint4)
__device__ uint4  g_U[8192 * 8];     // [-2x | xn, 1, 0...]
__device__ uint4  g_V[16384 * 8];    // [y | 1, yn, 0...] (p then a)
__device__ float2 g_WR[8192];        // (gamma*L2E, beta*L2E) per p_star row
__device__ float  g_LC[16384];       // column log-weight * L2E
__device__ double g_acc[4];          // 0=nonlink_pp 1=link_pp 2=nonlink_ap 3=link_ap
__device__ unsigned int g_arrive;

__device__ __forceinline__ float fast_sqrt(float x) {
    float r; asm("sqrt.approx.f32 %0, %1;" : "=f"(r) : "f"(x)); return r;
}
__device__ __forceinline__ float fast_exp2(float x) {
    float r; asm("ex2.approx.f32 %0, %1;" : "=f"(r) : "f"(x)); return r;
}
__device__ __forceinline__ uint32_t smem_u32(const void* p) {
    uint32_t r;
    asm("{ .reg .u64 t; cvta.to.shared.u64 t, %1; cvt.u32.u64 %0, t; }" : "=r"(r) : "l"(p));
    return r;
}
__device__ __forceinline__ void ldsm_x4(uint32_t* d, uint32_t addr) {
    asm volatile("ldmatrix.sync.aligned.m8n8.x4.shared.b16 {%0,%1,%2,%3}, [%4];"
                 : "=r"(d[0]), "=r"(d[1]), "=r"(d[2]), "=r"(d[3]) : "r"(addr));
}
__device__ __forceinline__ void ldsm_x2(uint32_t* d, uint32_t addr) {
    asm volatile("ldmatrix.sync.aligned.m8n8.x2.shared.b16 {%0,%1}, [%2];"
                 : "=r"(d[0]), "=r"(d[1]) : "r"(addr));
}
__device__ __forceinline__ void mma_bf16(float* c, const uint32_t* a, const uint32_t* b) {
    asm volatile(
        "mma.sync.aligned.m16n8k16.row.col.f32.bf16.bf16.f32 "
        "{%0,%1,%2,%3}, {%4,%5,%6,%7}, {%8,%9}, {%0,%1,%2,%3};"
        : "+f"(c[0]), "+f"(c[1]), "+f"(c[2]), "+f"(c[3])
        : "r"(a[0]), "r"(a[1]), "r"(a[2]), "r"(a[3]), "r"(b[0]), "r"(b[1]));
}

__device__ __forceinline__ float block_reduce(float v, float* sh) {
    #pragma unroll
    for (int off = 16; off > 0; off >>= 1)
        v += __shfl_down_sync(0xffffffffu, v, off);
    int lane = threadIdx.x & 31;
    int w = threadIdx.x >> 5;
    if (lane == 0) sh[w] = v;
    __syncthreads();
    if (w == 0) {
        v = (lane < (int)(TPB >> 5)) ? sh[lane] : 0.f;
        #pragma unroll
        for (int off = 4; off > 0; off >>= 1)
            v += __shfl_down_sync(0xffffffffu, v, off);
    }
    return v;
}

// ---------------- prep: 32-dim augmented hi/lo rows ----------------
__device__ __forceinline__ void pack32(uint4* dst, const float* vals) {
    uint16_t hb[32], lb[32];
    #pragma unroll
    for (int k = 0; k < 32; k++) {
        __nv_bfloat16 h = __float2bfloat16(vals[k]);
        __nv_bfloat16 l = __float2bfloat16(vals[k] - __bfloat162float(h));
        hb[k] = *reinterpret_cast<uint16_t*>(&h);
        lb[k] = *reinterpret_cast<uint16_t*>(&l);
    }
    uint32_t w[8];
    #pragma unroll
    for (int q = 0; q < 2; q++) {
        #pragma unroll
        for (int k = 0; k < 8; k++)
            w[k] = (uint32_t)hb[q*16 + 2*k] | ((uint32_t)hb[q*16 + 2*k + 1] << 16);
        dst[2*q]     = make_uint4(w[0], w[1], w[2], w[3]);
        dst[2*q + 1] = make_uint4(w[4], w[5], w[6], w[7]);
    }
    #pragma unroll
    for (int q = 0; q < 2; q++) {
        #pragma unroll
        for (int k = 0; k < 8; k++)
            w[k] = (uint32_t)lb[q*16 + 2*k] | ((uint32_t)lb[q*16 + 2*k + 1] << 16);
        dst[4 + 2*q]     = make_uint4(w[0], w[1], w[2], w[3]);
        dst[4 + 2*q + 1] = make_uint4(w[4], w[5], w[6], w[7]);
    }
}

__global__ void prep_kernel(const float* __restrict__ p_star,
                            const float* __restrict__ p,
                            const float* __restrict__ a,
                            const float* __restrict__ beta,
                            const float* __restrict__ gamma) {
    int idx = blockIdx.x * 256 + threadIdx.x;
    float vals[32];
    #pragma unroll
    for (int k = 0; k < 32; k++) vals[k] = 0.f;
    if (idx < 8192) {
        const float* x = p_star + (size_t)idx * DIM;
        float xn = 0.f;
        #pragma unroll
        for (int k = 0; k < DIM; k++) { float v = x[k]; xn += v*v; vals[k] = -2.f*v; }
        vals[16] = xn; vals[17] = 1.f;
        pack32(g_U + (size_t)idx * 8, vals);
        g_WR[idx] = make_float2(gamma[idx] * L2E, beta[idx] * L2E);
    } else if (idx < 24576) {
        int j = idx - 8192;
        const float* y = (j < N_PP) ? (p + (size_t)j * DIM) : (a + (size_t)(j - N_PP) * DIM);
        float yn = 0.f;
        #pragma unroll
        for (int k = 0; k < DIM; k++) { float v = y[k]; yn += v*v; vals[k] = v; }
        vals[16] = 1.f; vals[17] = yn;
        pack32(g_V + (size_t)j * 8, vals);
        g_LC[j] = ((j < N_PP) ? gamma[N_PP + j] : beta[j]) * L2E;
    }
}

// ---------------- tile body ----------------
template <bool MASKED>
__device__ __forceinline__ float tile_body(
    char* smem, uint32_t sbase, bool is_pp, int row0, int col0)
{
    const int tid = threadIdx.x;
    const int lane = tid & 31;
    const int w = tid >> 5;

    // A fragments: (chunk, half) -> 16B cols: h0:0-1, h1:2-3, l0:4-5, l1:6-7
    uint32_t ah0[4], ah1[4], al0[4], al1[4];
    {
        int arow = w * 16 + (lane & 15);
        int asel = lane >> 4;
        uint32_t rbase = sbase + SM_A + (uint32_t)arow * 128;
        uint32_t rx = (uint32_t)(arow & 7);
        ldsm_x4(ah0, rbase + (((0 + asel) ^ rx) << 4));
        ldsm_x4(ah1, rbase + (((2 + asel) ^ rx) << 4));
        ldsm_x4(al0, rbase + (((4 + asel) ^ rx) << 4));
        ldsm_x4(al1, rbase + (((6 + asel) ^ rx) << 4));
    }
    const int rl = w * 16 + (lane >> 2);
    const float2 wl2 = g_WR[row0 + rl];
    const float2 wh2 = g_WR[row0 + rl + 8];
    const float wr_lo = is_pp ? wl2.x : wl2.y;
    const float wr_hi = is_pp ? wh2.x : wh2.y;
    const int rg_lo = row0 + rl, rg_hi = rg_lo + 8;

    float acc_lo = 0.f, acc_hi = 0.f;
    #pragma unroll 2
    for (int ct = 0; ct < COLS_PT / 8; ct++) {
        const int j0 = ct * 8;
        uint32_t bh0[2], bh1[2], bl0[2], bl1[2];
        {
            int brow = j0 + (lane & 7);
            int bsel = (lane >> 3) & 1;
            uint32_t rbase = sbase + SM_B + (uint32_t)brow * 128;
            uint32_t rx = (uint32_t)(brow & 7);
            ldsm_x2(bh0, rbase + (((0 + bsel) ^ rx) << 4));
            ldsm_x2(bh1, rbase + (((2 + bsel) ^ rx) << 4));
            ldsm_x2(bl0, rbase + (((4 + bsel) ^ rx) << 4));
            ldsm_x2(bl1, rbase + (((6 + bsel) ^ rx) << 4));
        }
        float c[4] = {0.f, 0.f, 0.f, 0.f};
        mma_bf16(c, ah0, bh0);   // hh chunk0
        mma_bf16(c, ah1, bh1);   // hh chunk1 (adds xn+yn)
        mma_bf16(c, ah0, bl0);   // h*lo chunk0
        mma_bf16(c, ah1, bl1);   // h*lo chunk1
        mma_bf16(c, al0, bh0);   // lo*h chunk0
        mma_bf16(c, al1, bh1);   // lo*h chunk1

        const int ca = j0 + ((lane & 3) << 1);
        float2 lw = *reinterpret_cast<float2*>(smem + SM_LW + ca * 4);

        float t0 = fast_exp2(fmaf(fast_sqrt(fabsf(c[0])), -L2E, lw.x));
        float t1 = fast_exp2(fmaf(fast_sqrt(fabsf(c[1])), -L2E, lw.y));
        float t2 = fast_exp2(fmaf(fast_sqrt(fabsf(c[2])), -L2E, lw.x));
        float t3 = fast_exp2(fmaf(fast_sqrt(fabsf(c[3])), -L2E, lw.y));
        if (MASKED) {
            int ja = col0 + ca, jb = ja + 1;
            if (ja <= rg_lo) t0 = 0.f;
            if (jb <= rg_lo) t1 = 0.f;
            if (ja <= rg_hi) t2 = 0.f;
            if (jb <= rg_hi) t3 = 0.f;
        }
        acc_lo += t0 + t1;
        acc_hi += t2 + t3;
    }
    return acc_lo * fast_exp2(wr_lo) + acc_hi * fast_exp2(wr_hi);
}

__global__ __launch_bounds__(TPB, 4) void fused_kernel(
    const float* __restrict__ p_star,
    const float* __restrict__ p,
    const float* __restrict__ a,
    const float* __restrict__ beta,
    const float* __restrict__ gamma,
    const int* __restrict__ e_pp,
    const int* __restrict__ e_ap,
    int E,
    float* __restrict__ out)
{
    extern __shared__ char smem[];
    const uint32_t sbase = smem_u32(smem);
    float* red = reinterpret_cast<float*>(smem + SM_RED);
    const int bid = blockIdx.x;
    const int tid = threadIdx.x;

    if (bid < N_PP_ACT + N_AP_T) {
        // ---------------- pair tile ----------------
        const bool is_pp = (bid < N_PP_ACT);
        int rb, cb;
        if (is_pp) {
            // group g = rb>>1 (2 rows), count 2*(32-g), cb in [g,32)
            int t = bid;
            int g = 0;
            #pragma unroll
            for (int i = 0; i < 32; i++) {
                int cnt = 2 * (32 - i);
                if (t < cnt) { g = i; break; }
                t -= cnt;
            }
            int wd = 32 - g;
            rb = g * 2 + t / wd;
            cb = g + t % wd;
        } else {
            int t = bid - N_PP_ACT;
            rb = t >> 5;
            cb = t & 31;
        }
        const int row0 = rb * ROWS_PT;
        const int col0 = cb * COLS_PT;
        const int vbase = (is_pp ? 0 : N_PP) + col0;

        // stage A (128 x 8 uint4, swizzled)
        {
            const uint4* src = g_U + (size_t)row0 * 8;
            for (int idx = tid; idx < ROWS_PT * 8; idx += TPB) {
                int row = idx >> 3, q = idx & 7;
                *reinterpret_cast<uint4*>(smem + SM_A + row * 128 + ((q ^ (row & 7)) << 4)) = src[idx];
            }
        }
        // stage B (256 x 8 uint4, swizzled)
        {
            const uint4* src = g_V + (size_t)vbase * 8;
            for (int idx = tid; idx < COLS_PT * 8; idx += TPB) {
                int row = idx >> 3, q = idx & 7;
                *reinterpret_cast<uint4*>(smem + SM_B + row * 128 + ((q ^ (row & 7)) << 4)) = src[idx];
            }
        }
        // stage column log-weights
        reinterpret_cast<float*>(smem + SM_LW)[tid] = g_LC[vbase + tid];
        __syncthreads();

        const bool straddle = is_pp && (cb == (rb >> 1));
        float acc = straddle
            ? tile_body<true >(smem, sbase, is_pp, row0, col0)
            : tile_body<false>(smem, sbase, is_pp, row0, col0);

        float bsum = block_reduce(acc, red);
        if (tid == 0)
            atomicAdd(&g_acc[is_pp ? 0 : 2], (double)bsum);
    } else {
        // ---------------- edge stripe (fp32 exact) ----------------
        const int eb = bid - (N_PP_ACT + N_AP_T);
        float acc_pp = 0.f, acc_ap = 0.f;
        for (int e = eb * TPB + tid; e < E; e += N_EDGE_T * TPB) {
            {
                int s = e_pp[e];
                int t = e_pp[E + e];
                const float4* xs = reinterpret_cast<const float4*>(p_star + (size_t)s * DIM);
                const float4* yt = reinterpret_cast<const float4*>(p + (size_t)t * DIM);
                float d2 = 0.f;
                #pragma unroll
                for (int k = 0; k < 4; k++) {
                    float4 xv = xs[k], yv = yt[k];
                    float dx = xv.x - yv.x, dy = xv.y - yv.y;
                    float dz = xv.z - yv.z, dw = xv.w - yv.w;
                    d2 += dx*dx + dy*dy + dz*dz + dw*dw;
                }
                acc_pp += gamma[s] + gamma[t + N_PP] - fast_sqrt(d2);
            }
            {
                int s = e_ap[e];
                int t = e_ap[E + e];
                const float4* xs = reinterpret_cast<const float4*>(p_star + (size_t)s * DIM);
                const float4* yt = reinterpret_cast<const float4*>(a + (size_t)(t - N_PP) * DIM);
                float d2 = 0.f;
                #pragma unroll
                for (int k = 0; k < 4; k++) {
                    float4 xv = xs[k], yv = yt[k];
                    float dx = xv.x - yv.x, dy = xv.y - yv.y;
                    float dz = xv.z - yv.z, dw = xv.w - yv.w;
                    d2 += dx*dx + dy*dy + dz*dz + dw*dw;
                }
                acc_ap += beta[s] + beta[t] - fast_sqrt(d2);
            }
        }
        float s_pp = block_reduce(acc_pp, red);
        __syncthreads();
        float s_ap = block_reduce(acc_ap, red);
        if (tid == 0) {
            atomicAdd(&g_acc[1], (double)s_pp);
            atomicAdd(&g_acc[3], (double)s_ap);
        }
    }

    // ---------------- arrival + finalize ----------------
    __syncthreads();
    if (tid == 0) {
        __threadfence();
        unsigned old = atomicAdd(&g_arrive, 1u);
        if (old == (unsigned)(NB_TOTAL - 1)) {
            double nll_pp = -(g_acc[1] - g_acc[0]);
            double nll_ap = -(g_acc[3] - g_acc[2]);
            out[0] = (float)(0.5 * nll_pp / (double)N_PP + 0.5 * nll_ap / (double)N_PP);
            g_acc[0] = 0.0; g_acc[1] = 0.0; g_acc[2] = 0.0; g_acc[3] = 0.0;
            g_arrive = 0u;
            __threadfence();
        }
    }
}

extern "C" void kernel_launch(void* const* d_in, const int* in_sizes, int n_in,
                              void* d_out, int out_size) {
    const float* p_star = (const float*)d_in[0];
    const float* p      = (const float*)d_in[1];
    const float* a      = (const float*)d_in[2];
    const float* beta   = (const float*)d_in[3];
    const float* gamma  = (const float*)d_in[4];
    const int*   e_pp   = (const int*)d_in[5];
    const int*   e_ap   = (const int*)d_in[6];
    int E = in_sizes[5] / 2;

    cudaFuncSetAttribute(fused_kernel,
                         cudaFuncAttributeMaxDynamicSharedMemorySize, SMEM_TOTAL);

    prep_kernel<<<96, 256>>>(p_star, p, a, beta, gamma);
    fused_kernel<<<NB_TOTAL, TPB, SMEM_TOTAL>>>(p_star, p, a, beta, gamma,
                                                e_pp, e_ap, E, (float*)d_out);
}

// round 14
// speedup vs baseline: 1.1371x; 1.1371x over previous
#include <cuda_runtime.h>
#include <cuda_bf16.h>
#include <cstdint>

#define N_PP 8192
#define DIM  16
#define L2E  1.4426950408889634f

#define TPB      256
#define ROWS_PT  128                 // rows per pair tile (8 warps x 16)
#define COLS_PT  512                 // cols per pair tile (64 n8 subtiles)
#define NB_ROW   (N_PP / ROWS_PT)    // 64
#define NB_COL   (N_PP / COLS_PT)    // 16
#define N_PP_ACT 544                 // active pp tiles
#define N_AP_T   (NB_ROW * NB_COL)   // 1024
#define N_EDGE_T 104
#define NB_TOTAL (N_PP_ACT + N_AP_T + N_EDGE_T)   // 1672

// row record: 80B = [hi bf16 x16 | lo bf16 x16 | meta float4] as 5 x uint4
#define REC 5
#define SM_A   0                      // 128 rows x 80B = 10240
#define SM_B   (128 * 80)             // 512 rows x 80B = 40960
#define SM_RED (SM_B + 512 * 80)      // 51200
#define SMEM_TOTAL (SM_RED + 64)

__device__ uint4 g_U[8192 * REC];     // p_star rows: -2x, meta (xn, gamma*L2E, beta*L2E)
__device__ uint4 g_V[16384 * REC];    // p then a rows: y, meta (yn, lw*L2E)
__device__ double g_acc[4];           // 0=nonlink_pp 1=link_pp 2=nonlink_ap 3=link_ap
__device__ unsigned int g_arrive;

__device__ __forceinline__ float fast_sqrt(float x) {
    float r; asm("sqrt.approx.f32 %0, %1;" : "=f"(r) : "f"(x)); return r;
}
__device__ __forceinline__ float fast_exp2(float x) {
    float r; asm("ex2.approx.f32 %0, %1;" : "=f"(r) : "f"(x)); return r;
}
__device__ __forceinline__ uint32_t smem_u32(const void* p) {
    uint32_t r;
    asm("{ .reg .u64 t; cvta.to.shared.u64 t, %1; cvt.u32.u64 %0, t; }" : "=r"(r) : "l"(p));
    return r;
}
__device__ __forceinline__ void ldsm_x4(uint32_t* d, uint32_t addr) {
    asm volatile("ldmatrix.sync.aligned.m8n8.x4.shared.b16 {%0,%1,%2,%3}, [%4];"
                 : "=r"(d[0]), "=r"(d[1]), "=r"(d[2]), "=r"(d[3]) : "r"(addr));
}
__device__ __forceinline__ void ldsm_x2(uint32_t* d, uint32_t addr) {
    asm volatile("ldmatrix.sync.aligned.m8n8.x2.shared.b16 {%0,%1}, [%2];"
                 : "=r"(d[0]), "=r"(d[1]) : "r"(addr));
}
__device__ __forceinline__ void mma_bf16(float* c, const uint32_t* a, const uint32_t* b) {
    asm volatile(
        "mma.sync.aligned.m16n8k16.row.col.f32.bf16.bf16.f32 "
        "{%0,%1,%2,%3}, {%4,%5,%6,%7}, {%8,%9}, {%0,%1,%2,%3};"
        : "+f"(c[0]), "+f"(c[1]), "+f"(c[2]), "+f"(c[3])
        : "r"(a[0]), "r"(a[1]), "r"(a[2]), "r"(a[3]), "r"(b[0]), "r"(b[1]));
}

__device__ __forceinline__ float block_reduce(float v, float* sh) {
    #pragma unroll
    for (int off = 16; off > 0; off >>= 1)
        v += __shfl_down_sync(0xffffffffu, v, off);
    int lane = threadIdx.x & 31;
    int w = threadIdx.x >> 5;
    if (lane == 0) sh[w] = v;
    __syncthreads();
    if (w == 0) {
        v = (lane < (int)(TPB >> 5)) ? sh[lane] : 0.f;
        #pragma unroll
        for (int off = 4; off > 0; off >>= 1)
            v += __shfl_down_sync(0xffffffffu, v, off);
    }
    return v;
}

// ---------------- prep: build packed hi/lo row records ----------------
__device__ __forceinline__ void pack_rec(uint4* dst, const float* vals, float4 meta) {
    uint16_t hb[16], lb[16];
    #pragma unroll
    for (int k = 0; k < 16; k++) {
        __nv_bfloat16 h = __float2bfloat16(vals[k]);
        __nv_bfloat16 l = __float2bfloat16(vals[k] - __bfloat162float(h));
        hb[k] = *reinterpret_cast<uint16_t*>(&h);
        lb[k] = *reinterpret_cast<uint16_t*>(&l);
    }
    uint32_t w[8];
    #pragma unroll
    for (int k = 0; k < 8; k++) w[k] = (uint32_t)hb[2*k] | ((uint32_t)hb[2*k+1] << 16);
    dst[0] = make_uint4(w[0], w[1], w[2], w[3]);
    dst[1] = make_uint4(w[4], w[5], w[6], w[7]);
    #pragma unroll
    for (int k = 0; k < 8; k++) w[k] = (uint32_t)lb[2*k] | ((uint32_t)lb[2*k+1] << 16);
    dst[2] = make_uint4(w[0], w[1], w[2], w[3]);
    dst[3] = make_uint4(w[4], w[5], w[6], w[7]);
    dst[4] = make_uint4(__float_as_uint(meta.x), __float_as_uint(meta.y),
                        __float_as_uint(meta.z), __float_as_uint(meta.w));
}

__global__ void prep_kernel(const float* __restrict__ p_star,
                            const float* __restrict__ p,
                            const float* __restrict__ a,
                            const float* __restrict__ beta,
                            const float* __restrict__ gamma) {
    int idx = blockIdx.x * 256 + threadIdx.x;
    float vals[16];
    if (idx < 8192) {
        const float* x = p_star + (size_t)idx * DIM;
        float xn = 0.f;
        #pragma unroll
        for (int k = 0; k < DIM; k++) { float v = x[k]; xn += v*v; vals[k] = -2.f*v; }
        pack_rec(g_U + (size_t)idx * REC, vals,
                 make_float4(xn, gamma[idx] * L2E, beta[idx] * L2E, 0.f));
    } else if (idx < 24576) {
        int j = idx - 8192;
        const float* y = (j < N_PP) ? (p + (size_t)j * DIM) : (a + (size_t)(j - N_PP) * DIM);
        float yn = 0.f;
        #pragma unroll
        for (int k = 0; k < DIM; k++) { float v = y[k]; yn += v*v; vals[k] = v; }
        float lw = (j < N_PP) ? gamma[N_PP + j] : beta[j];
        pack_rec(g_V + (size_t)j * REC, vals, make_float4(yn, lw * L2E, 0.f, 0.f));
    }
}

// ---------------- tile body (split accumulators: wr hoisted) ----------------
template <bool MASKED>
__device__ __forceinline__ float tile_body(
    char* smem, uint32_t sbase, bool is_pp, int row0, int col0)
{
    const int tid = threadIdx.x;
    const int lane = tid & 31;
    const int w = tid >> 5;

    uint32_t ah[4], al[4];
    {
        uint32_t aaddr = sbase + SM_A + (uint32_t)(w * 16 + (lane & 15)) * 80
                       + ((uint32_t)(lane >> 4) << 4);
        ldsm_x4(ah, aaddr);
        ldsm_x4(al, aaddr + 32);
    }
    const int rl = w * 16 + (lane >> 2);
    float4 mlo = *reinterpret_cast<float4*>(smem + SM_A + rl * 80 + 64);
    float4 mhi = *reinterpret_cast<float4*>(smem + SM_A + (rl + 8) * 80 + 64);
    const float xn_lo = mlo.x, xn_hi = mhi.x;
    const float wr_lo = is_pp ? mlo.y : mlo.z;
    const float wr_hi = is_pp ? mhi.y : mhi.z;
    const int rg_lo = row0 + rl, rg_hi = rg_lo + 8;

    float acc_lo = 0.f, acc_hi = 0.f;
    #pragma unroll 2
    for (int ct = 0; ct < COLS_PT / 8; ct++) {
        const int j0 = ct * 8;
        uint32_t bh[2], bl[2];
        uint32_t baddr = sbase + SM_B + (uint32_t)(j0 + (lane & 7)) * 80
                       + ((uint32_t)((lane >> 3) & 1) << 4);
        ldsm_x2(bh, baddr);
        ldsm_x2(bl, baddr + 32);

        float c[4] = {0.f, 0.f, 0.f, 0.f};
        mma_bf16(c, ah, bh);
        mma_bf16(c, ah, bl);
        mma_bf16(c, al, bh);

        const int ca = j0 + ((lane & 3) << 1);
        float2 ma = *reinterpret_cast<float2*>(smem + SM_B + ca * 80 + 64);       // (yn, lw)
        float2 mb = *reinterpret_cast<float2*>(smem + SM_B + (ca + 1) * 80 + 64);

        float n00 = xn_lo + ma.x, n01 = xn_lo + mb.x;
        float n10 = xn_hi + ma.x, n11 = xn_hi + mb.x;

        float t0 = fast_exp2(fmaf(fast_sqrt(fabsf(c[0] + n00)), -L2E, ma.y));
        float t1 = fast_exp2(fmaf(fast_sqrt(fabsf(c[1] + n01)), -L2E, mb.y));
        float t2 = fast_exp2(fmaf(fast_sqrt(fabsf(c[2] + n10)), -L2E, ma.y));
        float t3 = fast_exp2(fmaf(fast_sqrt(fabsf(c[3] + n11)), -L2E, mb.y));
        if (MASKED) {
            int ja = col0 + ca, jb = ja + 1;
            if (ja <= rg_lo) t0 = 0.f;
            if (jb <= rg_lo) t1 = 0.f;
            if (ja <= rg_hi) t2 = 0.f;
            if (jb <= rg_hi) t3 = 0.f;
        }
        acc_lo += t0 + t1;
        acc_hi += t2 + t3;
    }
    return acc_lo * fast_exp2(wr_lo) + acc_hi * fast_exp2(wr_hi);
}

__global__ __launch_bounds__(TPB, 4) void fused_kernel(
    const float* __restrict__ p_star,
    const float* __restrict__ p,
    const float* __restrict__ a,
    const float* __restrict__ beta,
    const float* __restrict__ gamma,
    const int* __restrict__ e_pp,
    const int* __restrict__ e_ap,
    int E,
    float* __restrict__ out)
{
    extern __shared__ char smem[];
    const uint32_t sbase = smem_u32(smem);
    float* red = reinterpret_cast<float*>(smem + SM_RED);
    const int bid = blockIdx.x;
    const int tid = threadIdx.x;

    if (bid < N_PP_ACT + N_AP_T) {
        const bool is_pp = (bid < N_PP_ACT);
        int rb, cb;
        if (is_pp) {
            int t = bid;
            int g = 0;
            #pragma unroll
            for (int i = 0; i < 16; i++) {
                int cnt = 4 * (16 - i);
                if (t < cnt) { g = i; break; }
                t -= cnt;
            }
            int wd = 16 - g;
            rb = g * 4 + t / wd;
            cb = g + t % wd;
        } else {
            int t = bid - N_PP_ACT;
            rb = t >> 4;
            cb = t & 15;
        }
        const int row0 = rb * ROWS_PT;
        const int col0 = cb * COLS_PT;
        const int vbase = (is_pp ? 0 : N_PP) + col0;

        {
            const uint4* src = g_U + (size_t)row0 * REC;
            for (int idx = tid; idx < ROWS_PT * REC; idx += TPB) {
                int row = idx / REC, q = idx % REC;
                *reinterpret_cast<uint4*>(smem + SM_A + row * 80 + q * 16) = src[idx];
            }
        }
        {
            const uint4* src = g_V + (size_t)vbase * REC;
            for (int idx = tid; idx < COLS_PT * REC; idx += TPB) {
                int row = idx / REC, q = idx % REC;
                *reinterpret_cast<uint4*>(smem + SM_B + row * 80 + q * 16) = src[idx];
            }
        }
        __syncthreads();

        const bool straddle = is_pp && (cb == (rb >> 2));
        float acc = straddle
            ? tile_body<true >(smem, sbase, is_pp, row0, col0)
            : tile_body<false>(smem, sbase, is_pp, row0, col0);

        float bsum = block_reduce(acc, red);
        if (tid == 0)
            atomicAdd(&g_acc[is_pp ? 0 : 2], (double)bsum);
    } else {
        const int eb = bid - (N_PP_ACT + N_AP_T);
        float acc_pp = 0.f, acc_ap = 0.f;
        for (int e = eb * TPB + tid; e < E; e += N_EDGE_T * TPB) {
            {
                int s = e_pp[e];
                int t = e_pp[E + e];
                const float4* xs = reinterpret_cast<const float4*>(p_star + (size_t)s * DIM);
                const float4* yt = reinterpret_cast<const float4*>(p + (size_t)t * DIM);
                float d2 = 0.f;
                #pragma unroll
                for (int k = 0; k < 4; k++) {
                    float4 xv = xs[k], yv = yt[k];
                    float dx = xv.x - yv.x, dy = xv.y - yv.y;
                    float dz = xv.z - yv.z, dw = xv.w - yv.w;
                    d2 += dx*dx + dy*dy + dz*dz + dw*dw;
                }
                acc_pp += gamma[s] + gamma[t + N_PP] - fast_sqrt(d2);
            }
            {
                int s = e_ap[e];
                int t = e_ap[E + e];
                const float4* xs = reinterpret_cast<const float4*>(p_star + (size_t)s * DIM);
                const float4* yt = reinterpret_cast<const float4*>(a + (size_t)(t - N_PP) * DIM);
                float d2 = 0.f;
                #pragma unroll
                for (int k = 0; k < 4; k++) {
                    float4 xv = xs[k], yv = yt[k];
                    float dx = xv.x - yv.x, dy = xv.y - yv.y;
                    float dz = xv.z - yv.z, dw = xv.w - yv.w;
                    d2 += dx*dx + dy*dy + dz*dz + dw*dw;
                }
                acc_ap += beta[s] + beta[t] - fast_sqrt(d2);
            }
        }
        float s_pp = block_reduce(acc_pp, red);
        __syncthreads();
        float s_ap = block_reduce(acc_ap, red);
        if (tid == 0) {
            atomicAdd(&g_acc[1], (double)s_pp);
            atomicAdd(&g_acc[3], (double)s_ap);
        }
    }

    __syncthreads();
    if (tid == 0) {
        __threadfence();
        unsigned old = atomicAdd(&g_arrive, 1u);
        if (old == (unsigned)(NB_TOTAL - 1)) {
            double nll_pp = -(g_acc[1] - g_acc[0]);
            double nll_ap = -(g_acc[3] - g_acc[2]);
            out[0] = (float)(0.5 * nll_pp / (double)N_PP + 0.5 * nll_ap / (double)N_PP);
            g_acc[0] = 0.0; g_acc[1] = 0.0; g_acc[2] = 0.0; g_acc[3] = 0.0;
            g_arrive = 0u;
            __threadfence();
        }
    }
}

extern "C" void kernel_launch(void* const* d_in, const int* in_sizes, int n_in,
                              void* d_out, int out_size) {
    const float* p_star = (const float*)d_in[0];
    const float* p      = (const float*)d_in[1];
    const float* a      = (const float*)d_in[2];
    const float* beta   = (const float*)d_in[3];
    const float* gamma  = (const float*)d_in[4];
    const int*   e_pp   = (const int*)d_in[5];
    const int*   e_ap   = (const int*)d_in[6];
    int E = in_sizes[5] / 2;

    cudaFuncSetAttribute(fused_kernel,
                         cudaFuncAttributeMaxDynamicSharedMemorySize, SMEM_TOTAL);

    prep_kernel<<<96, 256>>>(p_star, p, a, beta, gamma);
    fused_kernel<<<NB_TOTAL, TPB, SMEM_TOTAL>>>(p_star, p, a, beta, gamma,
                                                e_pp, e_ap, E, (float*)d_out);
}

// round 15
// speedup vs baseline: 1.5103x; 1.3283x over previous
#include <cuda_runtime.h>
#include <cuda_bf16.h>
#include <cstdint>

#define N_PP 8192
#define DIM  16
#define L2E  1.4426950408889634f

#define TPB      256
#define ROWS_PT  128                 // rows per pair tile (8 warps x 16)
#define COLS_PT  512                 // cols per pair tile (64 n8 subtiles)
#define NB_ROW   (N_PP / ROWS_PT)    // 64
#define NB_COL   (N_PP / COLS_PT)    // 16
#define N_PP_ACT 544                 // active pp tiles
#define N_AP_T   (NB_ROW * NB_COL)   // 1024
#define N_EDGE_T 104
#define NB_TOTAL (N_PP_ACT + N_AP_T + N_EDGE_T)   // 1672

// A record: 80B = [hi bf16 x16 | lo bf16 x16 | meta float4]  (5 x uint4)
// B record: 48B = [hi bf16 x16 | meta float4(yn, lw, 0, 0)]  (3 x uint4)
#define REC_A 5
#define REC_B 3
#define SM_A   0                      // 128 x 80B = 10240
#define SM_B   (128 * 80)             // 512 x 48B = 24576
#define SM_RED (SM_B + 512 * 48)      // 34816
#define SMEM_TOTAL (SM_RED + 64)

__device__ uint4 g_U[8192 * REC_A];   // p_star rows: -2x hi|lo, meta(xn, g*L2E, b*L2E)
__device__ uint4 g_V[16384 * REC_B];  // p then a rows: y hi, meta(yn, lw*L2E)
__device__ double g_acc[4];           // 0=nonlink_pp 1=link_pp 2=nonlink_ap 3=link_ap
__device__ unsigned int g_arrive;

__device__ __forceinline__ float fast_sqrt(float x) {
    float r; asm("sqrt.approx.f32 %0, %1;" : "=f"(r) : "f"(x)); return r;
}
__device__ __forceinline__ float fast_exp2(float x) {
    float r; asm("ex2.approx.f32 %0, %1;" : "=f"(r) : "f"(x)); return r;
}
__device__ __forceinline__ uint32_t smem_u32(const void* p) {
    uint32_t r;
    asm("{ .reg .u64 t; cvta.to.shared.u64 t, %1; cvt.u32.u64 %0, t; }" : "=r"(r) : "l"(p));
    return r;
}
__device__ __forceinline__ void ldsm_x4(uint32_t* d, uint32_t addr) {
    asm volatile("ldmatrix.sync.aligned.m8n8.x4.shared.b16 {%0,%1,%2,%3}, [%4];"
                 : "=r"(d[0]), "=r"(d[1]), "=r"(d[2]), "=r"(d[3]) : "r"(addr));
}
__device__ __forceinline__ void ldsm_x2(uint32_t* d, uint32_t addr) {
    asm volatile("ldmatrix.sync.aligned.m8n8.x2.shared.b16 {%0,%1}, [%2];"
                 : "=r"(d[0]), "=r"(d[1]) : "r"(addr));
}
__device__ __forceinline__ void mma_bf16(float* c, const uint32_t* a, const uint32_t* b) {
    asm volatile(
        "mma.sync.aligned.m16n8k16.row.col.f32.bf16.bf16.f32 "
        "{%0,%1,%2,%3}, {%4,%5,%6,%7}, {%8,%9}, {%0,%1,%2,%3};"
        : "+f"(c[0]), "+f"(c[1]), "+f"(c[2]), "+f"(c[3])
        : "r"(a[0]), "r"(a[1]), "r"(a[2]), "r"(a[3]), "r"(b[0]), "r"(b[1]));
}

__device__ __forceinline__ float block_reduce(float v, float* sh) {
    #pragma unroll
    for (int off = 16; off > 0; off >>= 1)
        v += __shfl_down_sync(0xffffffffu, v, off);
    int lane = threadIdx.x & 31;
    int w = threadIdx.x >> 5;
    if (lane == 0) sh[w] = v;
    __syncthreads();
    if (w == 0) {
        v = (lane < (int)(TPB >> 5)) ? sh[lane] : 0.f;
        #pragma unroll
        for (int off = 4; off > 0; off >>= 1)
            v += __shfl_down_sync(0xffffffffu, v, off);
    }
    return v;
}

// ---------------- prep ----------------
__global__ void prep_kernel(const float* __restrict__ p_star,
                            const float* __restrict__ p,
                            const float* __restrict__ a,
                            const float* __restrict__ beta,
                            const float* __restrict__ gamma) {
    int idx = blockIdx.x * 256 + threadIdx.x;
    if (idx < 8192) {
        const float* x = p_star + (size_t)idx * DIM;
        float vals[16];
        float xn = 0.f;
        #pragma unroll
        for (int k = 0; k < DIM; k++) { float v = x[k]; xn += v*v; vals[k] = -2.f*v; }
        uint16_t hb[16], lb[16];
        #pragma unroll
        for (int k = 0; k < 16; k++) {
            __nv_bfloat16 h = __float2bfloat16(vals[k]);
            __nv_bfloat16 l = __float2bfloat16(vals[k] - __bfloat162float(h));
            hb[k] = *reinterpret_cast<uint16_t*>(&h);
            lb[k] = *reinterpret_cast<uint16_t*>(&l);
        }
        uint32_t w[8];
        uint4* dst = g_U + (size_t)idx * REC_A;
        #pragma unroll
        for (int k = 0; k < 8; k++) w[k] = (uint32_t)hb[2*k] | ((uint32_t)hb[2*k+1] << 16);
        dst[0] = make_uint4(w[0], w[1], w[2], w[3]);
        dst[1] = make_uint4(w[4], w[5], w[6], w[7]);
        #pragma unroll
        for (int k = 0; k < 8; k++) w[k] = (uint32_t)lb[2*k] | ((uint32_t)lb[2*k+1] << 16);
        dst[2] = make_uint4(w[0], w[1], w[2], w[3]);
        dst[3] = make_uint4(w[4], w[5], w[6], w[7]);
        dst[4] = make_uint4(__float_as_uint(xn), __float_as_uint(gamma[idx] * L2E),
                            __float_as_uint(beta[idx] * L2E), 0u);
    } else if (idx < 24576) {
        int j = idx - 8192;
        const float* y = (j < N_PP) ? (p + (size_t)j * DIM) : (a + (size_t)(j - N_PP) * DIM);
        float yn = 0.f;
        uint16_t hb[16];
        #pragma unroll
        for (int k = 0; k < DIM; k++) {
            float v = y[k]; yn += v*v;
            __nv_bfloat16 h = __float2bfloat16(v);
            hb[k] = *reinterpret_cast<uint16_t*>(&h);
        }
        uint32_t w[8];
        #pragma unroll
        for (int k = 0; k < 8; k++) w[k] = (uint32_t)hb[2*k] | ((uint32_t)hb[2*k+1] << 16);
        uint4* dst = g_V + (size_t)j * REC_B;
        dst[0] = make_uint4(w[0], w[1], w[2], w[3]);
        dst[1] = make_uint4(w[4], w[5], w[6], w[7]);
        float lw = (j < N_PP) ? gamma[N_PP + j] : beta[j];
        dst[2] = make_uint4(__float_as_uint(yn), __float_as_uint(lw * L2E), 0u, 0u);
    }
}

// ---------------- tile body ----------------
template <bool MASKED>
__device__ __forceinline__ float tile_body(
    char* smem, uint32_t sbase, bool is_pp, int row0, int col0)
{
    const int tid = threadIdx.x;
    const int lane = tid & 31;
    const int w = tid >> 5;

    uint32_t ah[4], al[4];
    {
        uint32_t aaddr = sbase + SM_A + (uint32_t)(w * 16 + (lane & 15)) * 80
                       + ((uint32_t)(lane >> 4) << 4);
        ldsm_x4(ah, aaddr);
        ldsm_x4(al, aaddr + 32);
    }
    const int rl = w * 16 + (lane >> 2);
    float4 mlo = *reinterpret_cast<float4*>(smem + SM_A + rl * 80 + 64);
    float4 mhi = *reinterpret_cast<float4*>(smem + SM_A + (rl + 8) * 80 + 64);
    const float xn_lo = mlo.x, xn_hi = mhi.x;
    const float wr_lo = is_pp ? mlo.y : mlo.z;
    const float wr_hi = is_pp ? mhi.y : mhi.z;
    const int rg_lo = row0 + rl, rg_hi = rg_lo + 8;

    float acc_lo = 0.f, acc_hi = 0.f;
    #pragma unroll 4
    for (int ct = 0; ct < COLS_PT / 8; ct++) {
        const int j0 = ct * 8;
        uint32_t bh[2];
        uint32_t baddr = sbase + SM_B + (uint32_t)(j0 + (lane & 7)) * 48
                       + ((uint32_t)((lane >> 3) & 1) << 4);
        ldsm_x2(bh, baddr);

        float c[4] = {0.f, 0.f, 0.f, 0.f};
        mma_bf16(c, ah, bh);   // hi*hi
        mma_bf16(c, al, bh);   // lo*hi (A-side correction)

        const int ca = j0 + ((lane & 3) << 1);
        float2 ma = *reinterpret_cast<float2*>(smem + SM_B + ca * 48 + 32);       // (yn, lw)
        float2 mb = *reinterpret_cast<float2*>(smem + SM_B + (ca + 1) * 48 + 32);

        float n00 = xn_lo + ma.x, n01 = xn_lo + mb.x;
        float n10 = xn_hi + ma.x, n11 = xn_hi + mb.x;

        float t0 = fast_exp2(fmaf(fast_sqrt(fabsf(c[0] + n00)), -L2E, ma.y));
        float t1 = fast_exp2(fmaf(fast_sqrt(fabsf(c[1] + n01)), -L2E, mb.y));
        float t2 = fast_exp2(fmaf(fast_sqrt(fabsf(c[2] + n10)), -L2E, ma.y));
        float t3 = fast_exp2(fmaf(fast_sqrt(fabsf(c[3] + n11)), -L2E, mb.y));
        if (MASKED) {
            int ja = col0 + ca, jb = ja + 1;
            if (ja <= rg_lo) t0 = 0.f;
            if (jb <= rg_lo) t1 = 0.f;
            if (ja <= rg_hi) t2 = 0.f;
            if (jb <= rg_hi) t3 = 0.f;
        }
        acc_lo += t0 + t1;
        acc_hi += t2 + t3;
    }
    return acc_lo * fast_exp2(wr_lo) + acc_hi * fast_exp2(wr_hi);
}

__global__ __launch_bounds__(TPB, 4) void fused_kernel(
    const float* __restrict__ p_star,
    const float* __restrict__ p,
    const float* __restrict__ a,
    const float* __restrict__ beta,
    const float* __restrict__ gamma,
    const int* __restrict__ e_pp,
    const int* __restrict__ e_ap,
    int E,
    float* __restrict__ out)
{
    extern __shared__ char smem[];
    const uint32_t sbase = smem_u32(smem);
    float* red = reinterpret_cast<float*>(smem + SM_RED);
    const int bid = blockIdx.x;
    const int tid = threadIdx.x;

    if (bid < N_PP_ACT + N_AP_T) {
        const bool is_pp = (bid < N_PP_ACT);
        int rb, cb;
        if (is_pp) {
            int t = bid;
            int g = 0;
            #pragma unroll
            for (int i = 0; i < 16; i++) {
                int cnt = 4 * (16 - i);
                if (t < cnt) { g = i; break; }
                t -= cnt;
            }
            int wd = 16 - g;
            rb = g * 4 + t / wd;
            cb = g + t % wd;
        } else {
            int t = bid - N_PP_ACT;
            rb = t >> 4;
            cb = t & 15;
        }
        const int row0 = rb * ROWS_PT;
        const int col0 = cb * COLS_PT;
        const int vbase = (is_pp ? 0 : N_PP) + col0;

        {
            const uint4* src = g_U + (size_t)row0 * REC_A;
            for (int idx = tid; idx < ROWS_PT * REC_A; idx += TPB) {
                int row = idx / REC_A, q = idx % REC_A;
                *reinterpret_cast<uint4*>(smem + SM_A + row * 80 + q * 16) = src[idx];
            }
        }
        {
            const uint4* src = g_V + (size_t)vbase * REC_B;
            for (int idx = tid; idx < COLS_PT * REC_B; idx += TPB) {
                int row = idx / REC_B, q = idx % REC_B;
                *reinterpret_cast<uint4*>(smem + SM_B + row * 48 + q * 16) = src[idx];
            }
        }
        __syncthreads();

        const bool straddle = is_pp && (cb == (rb >> 2));
        float acc = straddle
            ? tile_body<true >(smem, sbase, is_pp, row0, col0)
            : tile_body<false>(smem, sbase, is_pp, row0, col0);

        float bsum = block_reduce(acc, red);
        if (tid == 0)
            atomicAdd(&g_acc[is_pp ? 0 : 2], (double)bsum);
    } else {
        const int eb = bid - (N_PP_ACT + N_AP_T);
        float acc_pp = 0.f, acc_ap = 0.f;
        for (int e = eb * TPB + tid; e < E; e += N_EDGE_T * TPB) {
            {
                int s = e_pp[e];
                int t = e_pp[E + e];
                const float4* xs = reinterpret_cast<const float4*>(p_star + (size_t)s * DIM);
                const float4* yt = reinterpret_cast<const float4*>(p + (size_t)t * DIM);
                float d2 = 0.f;
                #pragma unroll
                for (int k = 0; k < 4; k++) {
                    float4 xv = xs[k], yv = yt[k];
                    float dx = xv.x - yv.x, dy = xv.y - yv.y;
                    float dz = xv.z - yv.z, dw = xv.w - yv.w;
                    d2 += dx*dx + dy*dy + dz*dz + dw*dw;
                }
                acc_pp += gamma[s] + gamma[t + N_PP] - fast_sqrt(d2);
            }
            {
                int s = e_ap[e];
                int t = e_ap[E + e];
                const float4* xs = reinterpret_cast<const float4*>(p_star + (size_t)s * DIM);
                const float4* yt = reinterpret_cast<const float4*>(a + (size_t)(t - N_PP) * DIM);
                float d2 = 0.f;
                #pragma unroll
                for (int k = 0; k < 4; k++) {
                    float4 xv = xs[k], yv = yt[k];
                    float dx = xv.x - yv.x, dy = xv.y - yv.y;
                    float dz = xv.z - yv.z, dw = xv.w - yv.w;
                    d2 += dx*dx + dy*dy + dz*dz + dw*dw;
                }
                acc_ap += beta[s] + beta[t] - fast_sqrt(d2);
            }
        }
        float s_pp = block_reduce(acc_pp, red);
        __syncthreads();
        float s_ap = block_reduce(acc_ap, red);
        if (tid == 0) {
            atomicAdd(&g_acc[1], (double)s_pp);
            atomicAdd(&g_acc[3], (double)s_ap);
        }
    }

    __syncthreads();
    if (tid == 0) {
        __threadfence();
        unsigned old = atomicAdd(&g_arrive, 1u);
        if (old == (unsigned)(NB_TOTAL - 1)) {
            double nll_pp = -(g_acc[1] - g_acc[0]);
            double nll_ap = -(g_acc[3] - g_acc[2]);
            out[0] = (float)(0.5 * nll_pp / (double)N_PP + 0.5 * nll_ap / (double)N_PP);
            g_acc[0] = 0.0; g_acc[1] = 0.0; g_acc[2] = 0.0; g_acc[3] = 0.0;
            g_arrive = 0u;
            __threadfence();
        }
    }
}

extern "C" void kernel_launch(void* const* d_in, const int* in_sizes, int n_in,
                              void* d_out, int out_size) {
    const float* p_star = (const float*)d_in[0];
    const float* p      = (const float*)d_in[1];
    const float* a      = (const float*)d_in[2];
    const float* beta   = (const float*)d_in[3];
    const float* gamma  = (const float*)d_in[4];
    const int*   e_pp   = (const int*)d_in[5];
    const int*   e_ap   = (const int*)d_in[6];
    int E = in_sizes[5] / 2;

    cudaFuncSetAttribute(fused_kernel,
                         cudaFuncAttributeMaxDynamicSharedMemorySize, SMEM_TOTAL);

    prep_kernel<<<96, 256>>>(p_star, p, a, beta, gamma);
    fused_kernel<<<NB_TOTAL, TPB, SMEM_TOTAL>>>(p_star, p, a, beta, gamma,
                                                e_pp, e_ap, E, (float*)d_out);
}

// round 16
// speedup vs baseline: 1.5979x; 1.0580x over previous
#include <cuda_runtime.h>
#include <cuda_bf16.h>
#include <cstdint>

#define N_PP 8192
#define DIM  16
#define L2E  1.4426950408889634f

#define TPB      256
#define ROWS_PT  128                 // rows per pair tile (8 warps x 16)
#define COLS_PT  512                 // cols per pair tile (64 n8 subtiles)
#define NB_ROW   (N_PP / ROWS_PT)    // 64
#define NB_COL   (N_PP / COLS_PT)    // 16
#define N_PP_ACT 544                 // active pp tiles
#define N_AP_T   (NB_ROW * NB_COL)   // 1024
#define N_EDGE_T 104
#define NB_TOTAL (N_PP_ACT + N_AP_T + N_EDGE_T)   // 1672

// A record: 48B = [-2x hi bf16 x16 | meta float4(xn, g*L2E, b*L2E, 0)]
// B record: 48B = [ y  hi bf16 x16 | meta float4(yn, lw*L2E, 0, 0)]
#define REC 3
#define SM_A   0                      // 128 x 48B = 6144
#define SM_B   (128 * 48)             // 512 x 48B = 24576
#define SM_RED (SM_B + 512 * 48)      // 30720
#define SMEM_TOTAL (SM_RED + 64)

__device__ uint4 g_U[8192 * REC];     // p_star rows
__device__ uint4 g_V[16384 * REC];    // p then a rows
__device__ double g_acc[4];           // 0=nonlink_pp 1=link_pp 2=nonlink_ap 3=link_ap
__device__ unsigned int g_arrive;

__device__ __forceinline__ float fast_sqrt(float x) {
    float r; asm("sqrt.approx.f32 %0, %1;" : "=f"(r) : "f"(x)); return r;
}
__device__ __forceinline__ float fast_exp2(float x) {
    float r; asm("ex2.approx.f32 %0, %1;" : "=f"(r) : "f"(x)); return r;
}
__device__ __forceinline__ uint32_t smem_u32(const void* p) {
    uint32_t r;
    asm("{ .reg .u64 t; cvta.to.shared.u64 t, %1; cvt.u32.u64 %0, t; }" : "=r"(r) : "l"(p));
    return r;
}
__device__ __forceinline__ void ldsm_x4(uint32_t* d, uint32_t addr) {
    asm volatile("ldmatrix.sync.aligned.m8n8.x4.shared.b16 {%0,%1,%2,%3}, [%4];"
                 : "=r"(d[0]), "=r"(d[1]), "=r"(d[2]), "=r"(d[3]) : "r"(addr));
}
__device__ __forceinline__ void ldsm_x2(uint32_t* d, uint32_t addr) {
    asm volatile("ldmatrix.sync.aligned.m8n8.x2.shared.b16 {%0,%1}, [%2];"
                 : "=r"(d[0]), "=r"(d[1]) : "r"(addr));
}
__device__ __forceinline__ void mma_bf16(float* c, const uint32_t* a, const uint32_t* b) {
    asm volatile(
        "mma.sync.aligned.m16n8k16.row.col.f32.bf16.bf16.f32 "
        "{%0,%1,%2,%3}, {%4,%5,%6,%7}, {%8,%9}, {%0,%1,%2,%3};"
        : "+f"(c[0]), "+f"(c[1]), "+f"(c[2]), "+f"(c[3])
        : "r"(a[0]), "r"(a[1]), "r"(a[2]), "r"(a[3]), "r"(b[0]), "r"(b[1]));
}

__device__ __forceinline__ float block_reduce(float v, float* sh) {
    #pragma unroll
    for (int off = 16; off > 0; off >>= 1)
        v += __shfl_down_sync(0xffffffffu, v, off);
    int lane = threadIdx.x & 31;
    int w = threadIdx.x >> 5;
    if (lane == 0) sh[w] = v;
    __syncthreads();
    if (w == 0) {
        v = (lane < (int)(TPB >> 5)) ? sh[lane] : 0.f;
        #pragma unroll
        for (int off = 4; off > 0; off >>= 1)
            v += __shfl_down_sync(0xffffffffu, v, off);
    }
    return v;
}

// ---------------- prep ----------------
__device__ __forceinline__ void pack16(uint4* dst, const float* vals, float4 meta) {
    uint16_t hb[16];
    #pragma unroll
    for (int k = 0; k < 16; k++) {
        __nv_bfloat16 h = __float2bfloat16(vals[k]);
        hb[k] = *reinterpret_cast<uint16_t*>(&h);
    }
    uint32_t w[8];
    #pragma unroll
    for (int k = 0; k < 8; k++) w[k] = (uint32_t)hb[2*k] | ((uint32_t)hb[2*k+1] << 16);
    dst[0] = make_uint4(w[0], w[1], w[2], w[3]);
    dst[1] = make_uint4(w[4], w[5], w[6], w[7]);
    dst[2] = make_uint4(__float_as_uint(meta.x), __float_as_uint(meta.y),
                        __float_as_uint(meta.z), __float_as_uint(meta.w));
}

__global__ void prep_kernel(const float* __restrict__ p_star,
                            const float* __restrict__ p,
                            const float* __restrict__ a,
                            const float* __restrict__ beta,
                            const float* __restrict__ gamma) {
    int idx = blockIdx.x * 256 + threadIdx.x;
    float vals[16];
    if (idx < 8192) {
        const float* x = p_star + (size_t)idx * DIM;
        float xn = 0.f;
        #pragma unroll
        for (int k = 0; k < DIM; k++) { float v = x[k]; xn += v*v; vals[k] = -2.f*v; }
        pack16(g_U + (size_t)idx * REC, vals,
               make_float4(xn, gamma[idx] * L2E, beta[idx] * L2E, 0.f));
    } else if (idx < 24576) {
        int j = idx - 8192;
        const float* y = (j < N_PP) ? (p + (size_t)j * DIM) : (a + (size_t)(j - N_PP) * DIM);
        float yn = 0.f;
        #pragma unroll
        for (int k = 0; k < DIM; k++) { float v = y[k]; yn += v*v; vals[k] = v; }
        float lw = (j < N_PP) ? gamma[N_PP + j] : beta[j];
        pack16(g_V + (size_t)j * REC, vals, make_float4(yn, lw * L2E, 0.f, 0.f));
    }
}

// ---------------- tile body ----------------
template <bool MASKED>
__device__ __forceinline__ float tile_body(
    char* smem, uint32_t sbase, bool is_pp, int row0, int col0)
{
    const int tid = threadIdx.x;
    const int lane = tid & 31;
    const int w = tid >> 5;

    uint32_t ah[4];
    ldsm_x4(ah, sbase + SM_A + (uint32_t)(w * 16 + (lane & 15)) * 48
                + ((uint32_t)(lane >> 4) << 4));
    const int rl = w * 16 + (lane >> 2);
    float4 mlo = *reinterpret_cast<float4*>(smem + SM_A + rl * 48 + 32);
    float4 mhi = *reinterpret_cast<float4*>(smem + SM_A + (rl + 8) * 48 + 32);
    const float xn_lo = mlo.x, xn_hi = mhi.x;
    const float wr_lo = is_pp ? mlo.y : mlo.z;
    const float wr_hi = is_pp ? mhi.y : mhi.z;
    const int rg_lo = row0 + rl, rg_hi = rg_lo + 8;

    float acc_lo = 0.f, acc_hi = 0.f;
    #pragma unroll 4
    for (int ct = 0; ct < COLS_PT / 8; ct++) {
        const int j0 = ct * 8;
        uint32_t bh[2];
        ldsm_x2(bh, sbase + SM_B + (uint32_t)(j0 + (lane & 7)) * 48
                    + ((uint32_t)((lane >> 3) & 1) << 4));

        const int ca = j0 + ((lane & 3) << 1);
        float2 ma = *reinterpret_cast<float2*>(smem + SM_B + ca * 48 + 32);       // (yn, lw)
        float2 mb = *reinterpret_cast<float2*>(smem + SM_B + (ca + 1) * 48 + 32);

        // seed accumulator with xn + yn; MMA adds -2x.y on top -> c = dist^2
        float c[4] = { xn_lo + ma.x, xn_lo + mb.x, xn_hi + ma.x, xn_hi + mb.x };
        mma_bf16(c, ah, bh);

        float t0 = fast_exp2(fmaf(fast_sqrt(fabsf(c[0])), -L2E, ma.y));
        float t1 = fast_exp2(fmaf(fast_sqrt(fabsf(c[1])), -L2E, mb.y));
        float t2 = fast_exp2(fmaf(fast_sqrt(fabsf(c[2])), -L2E, ma.y));
        float t3 = fast_exp2(fmaf(fast_sqrt(fabsf(c[3])), -L2E, mb.y));
        if (MASKED) {
            int ja = col0 + ca, jb = ja + 1;
            if (ja <= rg_lo) t0 = 0.f;
            if (jb <= rg_lo) t1 = 0.f;
            if (ja <= rg_hi) t2 = 0.f;
            if (jb <= rg_hi) t3 = 0.f;
        }
        acc_lo += t0 + t1;
        acc_hi += t2 + t3;
    }
    return acc_lo * fast_exp2(wr_lo) + acc_hi * fast_exp2(wr_hi);
}

__global__ __launch_bounds__(TPB, 4) void fused_kernel(
    const float* __restrict__ p_star,
    const float* __restrict__ p,
    const float* __restrict__ a,
    const float* __restrict__ beta,
    const float* __restrict__ gamma,
    const int* __restrict__ e_pp,
    const int* __restrict__ e_ap,
    int E,
    float* __restrict__ out)
{
    extern __shared__ char smem[];
    const uint32_t sbase = smem_u32(smem);
    float* red = reinterpret_cast<float*>(smem + SM_RED);
    const int bid = blockIdx.x;
    const int tid = threadIdx.x;

    if (bid < N_PP_ACT + N_AP_T) {
        const bool is_pp = (bid < N_PP_ACT);
        int rb, cb;
        if (is_pp) {
            int t = bid;
            int g = 0;
            #pragma unroll
            for (int i = 0; i < 16; i++) {
                int cnt = 4 * (16 - i);
                if (t < cnt) { g = i; break; }
                t -= cnt;
            }
            int wd = 16 - g;
            rb = g * 4 + t / wd;
            cb = g + t % wd;
        } else {
            int t = bid - N_PP_ACT;
            rb = t >> 4;
            cb = t & 15;
        }
        const int row0 = rb * ROWS_PT;
        const int col0 = cb * COLS_PT;
        const int vbase = (is_pp ? 0 : N_PP) + col0;

        {
            const uint4* src = g_U + (size_t)row0 * REC;
            for (int idx = tid; idx < ROWS_PT * REC; idx += TPB) {
                int row = idx / REC, q = idx % REC;
                *reinterpret_cast<uint4*>(smem + SM_A + row * 48 + q * 16) = src[idx];
            }
        }
        {
            const uint4* src = g_V + (size_t)vbase * REC;
            for (int idx = tid; idx < COLS_PT * REC; idx += TPB) {
                int row = idx / REC, q = idx % REC;
                *reinterpret_cast<uint4*>(smem + SM_B + row * 48 + q * 16) = src[idx];
            }
        }
        __syncthreads();

        const bool straddle = is_pp && (cb == (rb >> 2));
        float acc = straddle
            ? tile_body<true >(smem, sbase, is_pp, row0, col0)
            : tile_body<false>(smem, sbase, is_pp, row0, col0);

        float bsum = block_reduce(acc, red);
        if (tid == 0)
            atomicAdd(&g_acc[is_pp ? 0 : 2], (double)bsum);
    } else {
        const int eb = bid - (N_PP_ACT + N_AP_T);
        float acc_pp = 0.f, acc_ap = 0.f;
        for (int e = eb * TPB + tid; e < E; e += N_EDGE_T * TPB) {
            {
                int s = e_pp[e];
                int t = e_pp[E + e];
                const float4* xs = reinterpret_cast<const float4*>(p_star + (size_t)s * DIM);
                const float4* yt = reinterpret_cast<const float4*>(p + (size_t)t * DIM);
                float d2 = 0.f;
                #pragma unroll
                for (int k = 0; k < 4; k++) {
                    float4 xv = xs[k], yv = yt[k];
                    float dx = xv.x - yv.x, dy = xv.y - yv.y;
                    float dz = xv.z - yv.z, dw = xv.w - yv.w;
                    d2 += dx*dx + dy*dy + dz*dz + dw*dw;
                }
                acc_pp += gamma[s] + gamma[t + N_PP] - fast_sqrt(d2);
            }
            {
                int s = e_ap[e];
                int t = e_ap[E + e];
                const float4* xs = reinterpret_cast<const float4*>(p_star + (size_t)s * DIM);
                const float4* yt = reinterpret_cast<const float4*>(a + (size_t)(t - N_PP) * DIM);
                float d2 = 0.f;
                #pragma unroll
                for (int k = 0; k < 4; k++) {
                    float4 xv = xs[k], yv = yt[k];
                    float dx = xv.x - yv.x, dy = xv.y - yv.y;
                    float dz = xv.z - yv.z, dw = xv.w - yv.w;
                    d2 += dx*dx + dy*dy + dz*dz + dw*dw;
                }
                acc_ap += beta[s] + beta[t] - fast_sqrt(d2);
            }
        }
        float s_pp = block_reduce(acc_pp, red);
        __syncthreads();
        float s_ap = block_reduce(acc_ap, red);
        if (tid == 0) {
            atomicAdd(&g_acc[1], (double)s_pp);
            atomicAdd(&g_acc[3], (double)s_ap);
        }
    }

    __syncthreads();
    if (tid == 0) {
        __threadfence();
        unsigned old = atomicAdd(&g_arrive, 1u);
        if (old == (unsigned)(NB_TOTAL - 1)) {
            double nll_pp = -(g_acc[1] - g_acc[0]);
            double nll_ap = -(g_acc[3] - g_acc[2]);
            out[0] = (float)(0.5 * nll_pp / (double)N_PP + 0.5 * nll_ap / (double)N_PP);
            g_acc[0] = 0.0; g_acc[1] = 0.0; g_acc[2] = 0.0; g_acc[3] = 0.0;
            g_arrive = 0u;
            __threadfence();
        }
    }
}

extern "C" void kernel_launch(void* const* d_in, const int* in_sizes, int n_in,
                              void* d_out, int out_size) {
    const float* p_star = (const float*)d_in[0];
    const float* p      = (const float*)d_in[1];
    const float* a      = (const float*)d_in[2];
    const float* beta   = (const float*)d_in[3];
    const float* gamma  = (const float*)d_in[4];
    const int*   e_pp   = (const int*)d_in[5];
    const int*   e_ap   = (const int*)d_in[6];
    int E = in_sizes[5] / 2;

    cudaFuncSetAttribute(fused_kernel,
                         cudaFuncAttributeMaxDynamicSharedMemorySize, SMEM_TOTAL);

    prep_kernel<<<96, 256>>>(p_star, p, a, beta, gamma);
    fused_kernel<<<NB_TOTAL, TPB, SMEM_TOTAL>>>(p_star, p, a, beta, gamma,
                                                e_pp, e_ap, E, (float*)d_out);
}